// round 5
// baseline (speedup 1.0000x reference)
#include <cuda_runtime.h>
#include <cuda_bf16.h>
#include <math.h>

#define NIMG   4
#define NPROP  2000
#define MAXGT  64
#define HH     512
#define WW     512
#define PPOS   66
#define NNEG   134
#define NROIS  200
#define MH     28
#define MW     28
#define EPSF   1e-8f

// Output layout (float32, concatenated flattened tuple):
//   rois    [4][200][4]     @ 0      (3200)
//   class   [4][200]        @ 3200   (800)
//   deltas  [4][200][4]     @ 4000   (3200)
//   masks   [4][200][28][28]@ 7200   (627200)
#define OFF_ROIS  0
#define OFF_CLS   3200
#define OFF_DEL   4000
#define OFF_MSK   7200

// XLA rewrites x / const into x * (1/const) (algebraic simplifier).
// Reproduce bit-exactly: these fold at compile time to the same f32 XLA uses.
#define RCP_033  (1.0f / 0.33f)   // 3.030303002...; 66*r rounds to 200.0 (NOT 199.99998!)
#define RCP_01   (1.0f / 0.1f)    // exactly 10.0f
#define RCP_02   (1.0f / 0.2f)    // exactly 5.0f
#define RCP_27   (1.0f / 27.0f)

// ---------------- device scratch (no allocations allowed) ----------------
__device__ int            g_best[NIMG][NPROP];
__device__ unsigned char  g_posf[NIMG][NPROP];
__device__ unsigned char  g_negf[NIMG][NPROP];
__device__ int            g_pos_idx[NIMG][PPOS];
__device__ int            g_pos_count[NIMG];
__device__ int            g_mask_fmt;   // 0=u8, 1=i32, 2=f32, 3=bf16

// ---------------- mask dtype probe helper (warp-collective) ----------------
// Mask values are only 0/1, so the byte stream discriminates the dtype:
//   any byte > 1                          -> float32 or bf16 (0x3F/0x80 bytes)
//     nonzero byte at p%4==1              -> bf16 (f32 0/1 has zeros there)
//   else: byte==1 at p%4!=0               -> uint8/bool
//   else                                  -> int32
__device__ __forceinline__ void probe_mask_fmt(const unsigned char* __restrict__ m,
                                               int lane) {
    int a = 0, b = 0, c = 0;
    for (int p = lane; p < 4096; p += 32) {
        unsigned char v = __ldg(m + p);
        if (v > 1) a = 1;
        if ((p & 3) == 1 && v != 0) b = 1;
        if ((p & 3) != 0 && v == 1) c = 1;
    }
    unsigned am = __ballot_sync(0xFFFFFFFFu, a);
    unsigned bm = __ballot_sync(0xFFFFFFFFu, b);
    unsigned cm = __ballot_sync(0xFFFFFFFFu, c);
    if (lane == 0) {
        int fmt;
        if (am) fmt = bm ? 3 : 2;
        else    fmt = cm ? 0 : 1;
        g_mask_fmt = fmt;
    }
}

__device__ __forceinline__ float mask_at(const void* m, int fmt, int idx) {
    switch (fmt) {
        case 0:  return (float)__ldg((const unsigned char*)m + idx);
        case 1:  return (float)__ldg((const int*)m + idx);
        case 3: {
            unsigned short u = __ldg((const unsigned short*)m + idx);
            __nv_bfloat16 v;
            *(unsigned short*)&v = u;
            return __bfloat162float(v);
        }
        default: return __ldg((const float*)m + idx);
    }
}

// ---------------- IoU / flags ----------------
__global__ void __launch_bounds__(128)
k_iou(const float* __restrict__ props,
      const int*   __restrict__ ids,
      const float* __restrict__ gtb) {
    const int img = blockIdx.y;
    const int i   = blockIdx.x * blockDim.x + threadIdx.x;

    __shared__ float4 sgt[MAXGT];
    __shared__ int    sfl[MAXGT];   // bit0: gt_valid, bit1: crowd
    if (threadIdx.x < MAXGT) {
        const float* g = gtb + (img * MAXGT + threadIdx.x) * 4;
        float4 b; b.x = g[0]; b.y = g[1]; b.z = g[2]; b.w = g[3];
        sgt[threadIdx.x] = b;
        int id = ids[img * MAXGT + threadIdx.x];
        bool bv = (b.x != 0.f) || (b.y != 0.f) || (b.z != 0.f) || (b.w != 0.f);
        sfl[threadIdx.x] = ((bv && id > 0) ? 1 : 0) | ((bv && id < 0) ? 2 : 0);
    }
    __syncthreads();
    if (i >= NPROP) return;

    const float* p = props + (img * NPROP + i) * 4;
    float py1 = p[0], px1 = p[1], py2 = p[2], px2 = p[3];
    bool prop_valid = (py1 != 0.f) || (px1 != 0.f) || (py2 != 0.f) || (px2 != 0.f);
    float a1 = __fmul_rn(__fsub_rn(py2, py1), __fsub_rn(px2, px1));

    float best = -INFINITY; int bi = 0;
    float crowd_max = -1.0f;
    #pragma unroll 8
    for (int j = 0; j < MAXGT; ++j) {
        float4 g = sgt[j];
        int fl = sfl[j];
        float ih = fmaxf(__fsub_rn(fminf(py2, g.z), fmaxf(py1, g.x)), 0.0f);
        float iw = fmaxf(__fsub_rn(fminf(px2, g.w), fmaxf(px1, g.y)), 0.0f);
        float inter = __fmul_rn(ih, iw);
        float a2 = __fmul_rn(__fsub_rn(g.z, g.x), __fsub_rn(g.w, g.y));
        float denom = __fadd_rn(__fsub_rn(__fadd_rn(a1, a2), inter), EPSF);
        float iou = __fdiv_rn(inter, denom);
        float ov = (fl & 1) ? iou : -1.0f;
        if (ov > best) { best = ov; bi = j; }
        float cv = (fl & 2) ? iou : -1.0f;
        crowd_max = fmaxf(crowd_max, cv);
    }
    bool pos = (best >= 0.5f) && prop_valid;
    bool neg = (best < 0.5f) && (crowd_max < 0.001f) && prop_valid && !pos;
    g_best[img][i] = bi;
    g_posf[img][i] = pos ? 1 : 0;
    g_negf[img][i] = neg ? 1 : 0;
}

// ------- fused: stable first-k selection + rois/class/deltas emit -------
__global__ void __launch_bounds__(256)
k_select_emit(const float* __restrict__ props,
              const int*   __restrict__ ids,
              const float* __restrict__ gtb,
              const unsigned char* __restrict__ masks_raw,
              float* __restrict__ out) {
    const int img = blockIdx.x;
    __shared__ int s_pos_idx[PPOS];
    __shared__ int s_neg_idx[NNEG];
    __shared__ int s_pos_count, s_neg_count;

    if (threadIdx.x < 32) {
        const int lane = threadIdx.x;
        int ptot = 0, ntot = 0;
        for (int base = 0; base < NPROP; base += 32) {
            int i = base + lane;
            int pf = (i < NPROP) ? g_posf[img][i] : 0;
            int nf = (i < NPROP) ? g_negf[img][i] : 0;
            unsigned pm = __ballot_sync(0xFFFFFFFFu, pf);
            unsigned nm = __ballot_sync(0xFFFFFFFFu, nf);
            unsigned lt = (1u << lane) - 1u;
            if (pf) { int r = ptot + __popc(pm & lt); if (r < PPOS) s_pos_idx[r] = i; }
            if (nf) { int r = ntot + __popc(nm & lt); if (r < NNEG) s_neg_idx[r] = i; }
            ptot += __popc(pm);
            ntot += __popc(nm);
        }
        if (lane == 0) {
            int pos_count = ptot < PPOS ? ptot : PPOS;
            // XLA: pos/0.33 -> pos * (1/0.33f).  At pos=66 this yields exactly
            // 200.0f (plain division yields 199.99998) -> neg_target 134 vs 133.
            int neg_target = (int)(__fmul_rn((float)pos_count, RCP_033)) - pos_count;
            int avail = ntot < NNEG ? ntot : NNEG;
            int neg_count = neg_target < 0 ? 0 : (neg_target < avail ? neg_target : avail);
            s_pos_count = pos_count;
            s_neg_count = neg_count;
            g_pos_count[img] = pos_count;
        }
    } else if (img == 0 && threadIdx.x >= 224) {
        probe_mask_fmt(masks_raw, threadIdx.x - 224);
    }
    __syncthreads();

    // Publish pos_idx for the mask kernel.
    if (threadIdx.x < PPOS) g_pos_idx[img][threadIdx.x] = s_pos_idx[threadIdx.x];

    const int k = threadIdx.x;   // 0..199 emit; others exit
    if (k >= NROIS) return;

    float r0 = 0.f, r1 = 0.f, r2 = 0.f, r3 = 0.f;
    float cls = 0.f;
    float d0 = 0.f, d1 = 0.f, d2 = 0.f, d3 = 0.f;

    if (k < PPOS) {
        if (k < s_pos_count) {
            int idx = s_pos_idx[k];
            const float* p = props + (img * NPROP + idx) * 4;
            r0 = p[0]; r1 = p[1]; r2 = p[2]; r3 = p[3];
            int bg = g_best[img][idx];
            cls = (float)ids[img * MAXGT + bg];
            const float* g = gtb + (img * MAXGT + bg) * 4;
            float gy1 = g[0], gx1 = g[1], gy2 = g[2], gx2 = g[3];
            float h  = fmaxf(__fsub_rn(r2, r0), EPSF);
            float w  = fmaxf(__fsub_rn(r3, r1), EPSF);
            float cy = __fadd_rn(r0, __fmul_rn(0.5f, h));
            float cx = __fadd_rn(r1, __fmul_rn(0.5f, w));
            float gh = fmaxf(__fsub_rn(gy2, gy1), EPSF);
            float gw = fmaxf(__fsub_rn(gx2, gx1), EPSF);
            float gcy = __fadd_rn(gy1, __fmul_rn(0.5f, gh));
            float gcx = __fadd_rn(gx1, __fmul_rn(0.5f, gw));
            // BBOX_STD division -> XLA reciprocal multiplies (10.0f, 5.0f exact)
            d0 = __fmul_rn(__fdiv_rn(__fsub_rn(gcy, cy), h), RCP_01);
            d1 = __fmul_rn(__fdiv_rn(__fsub_rn(gcx, cx), w), RCP_01);
            d2 = __fmul_rn(logf(__fdiv_rn(gh, h)), RCP_02);
            d3 = __fmul_rn(logf(__fdiv_rn(gw, w)), RCP_02);
        }
    } else {
        int j = k - PPOS;
        if (j < s_neg_count) {
            int idx = s_neg_idx[j];
            const float* p = props + (img * NPROP + idx) * 4;
            r0 = p[0]; r1 = p[1]; r2 = p[2]; r3 = p[3];
        }
    }
    int row = img * NROIS + k;
    float* rois = out + OFF_ROIS + row * 4;
    rois[0] = r0; rois[1] = r1; rois[2] = r2; rois[3] = r3;
    out[OFF_CLS + row] = cls;
    float* del = out + OFF_DEL + row * 4;
    del[0] = d0; del[1] = d1; del[2] = d2; del[3] = d3;
}

// ---------------- mask crop-resize ----------------
__global__ void __launch_bounds__(MH * MW)
k_masks(const float* __restrict__ props,
        const void*  __restrict__ masks,
        float* __restrict__ out) {
    const int img = blockIdx.y;
    const int k   = blockIdx.x;   // 0..199
    const int t   = threadIdx.x;  // 0..783 pixel index
    float val = 0.0f;
    if (k < g_pos_count[img]) {   // k >= PPOS never passes (pos_count <= 66)
        int fmt = g_mask_fmt;
        int idx = g_pos_idx[img][k];
        int g   = g_best[img][idx];
        const float* p = props + (img * NPROP + idx) * 4;
        float y1 = p[0], x1 = p[1], y2 = p[2], x2 = p[3];
        int i = t / MW, j = t % MW;
        // XLA: arange/27 -> arange * (1/27f)
        float iy = __fmul_rn((float)i, RCP_27);
        float ix = __fmul_rn((float)j, RCP_27);
        float ys = __fmul_rn(__fadd_rn(y1, __fmul_rn(iy, __fsub_rn(y2, y1))), (float)(HH - 1));
        float xs = __fmul_rn(__fadd_rn(x1, __fmul_rn(ix, __fsub_rn(x2, x1))), (float)(WW - 1));
        float y0f = floorf(ys), x0f = floorf(xs);
        float ly = __fsub_rn(ys, y0f);
        float lx = __fsub_rn(xs, x0f);
        int y0  = min(max((int)y0f, 0), HH - 1);
        int y1i = min(y0 + 1, HH - 1);
        int x0  = min(max((int)x0f, 0), WW - 1);
        int x1i = min(x0 + 1, WW - 1);
        int rowbase0 = (img * HH + y0)  * WW;
        int rowbase1 = (img * HH + y1i) * WW;
        float v00 = mask_at(masks, fmt, (rowbase0 + x0)  * MAXGT + g);
        float v01 = mask_at(masks, fmt, (rowbase0 + x1i) * MAXGT + g);
        float v10 = mask_at(masks, fmt, (rowbase1 + x0)  * MAXGT + g);
        float v11 = mask_at(masks, fmt, (rowbase1 + x1i) * MAXGT + g);
        float omlx = __fsub_rn(1.0f, lx);
        float omly = __fsub_rn(1.0f, ly);
        float top = __fadd_rn(__fmul_rn(v00, omlx), __fmul_rn(v01, lx));
        float bot = __fadd_rn(__fmul_rn(v10, omlx), __fmul_rn(v11, lx));
        val = rintf(__fadd_rn(__fmul_rn(top, omly), __fmul_rn(bot, ly)));  // round half-to-even
    }
    out[OFF_MSK + (img * NROIS + k) * (MH * MW) + t] = val;
}

// ---------------- launch ----------------
extern "C" void kernel_launch(void* const* d_in, const int* in_sizes, int n_in,
                              void* d_out, int out_size) {
    const float* props = (const float*)d_in[0];
    const int*   ids   = (const int*)  d_in[1];
    const float* gtb   = (const float*)d_in[2];
    const void*  masks = d_in[3];
    float* out = (float*)d_out;

    k_iou<<<dim3((NPROP + 127) / 128, NIMG), 128>>>(props, ids, gtb);
    k_select_emit<<<NIMG, 256>>>(props, ids, gtb,
                                 (const unsigned char*)masks, out);
    k_masks<<<dim3(NROIS, NIMG), MH * MW>>>(props, masks, out);
}

// round 6
// speedup vs baseline: 1.7021x; 1.7021x over previous
#include <cuda_runtime.h>
#include <cuda_bf16.h>
#include <math.h>

#define NIMG   4
#define NPROP  2000
#define MAXGT  64
#define HH     512
#define WW     512
#define PPOS   66
#define NNEG   134
#define NROIS  200
#define MH     28
#define MW     28
#define EPSF   1e-8f

// Output layout (float32, concatenated flattened tuple):
//   rois    [4][200][4]     @ 0      (3200)
//   class   [4][200]        @ 3200   (800)
//   deltas  [4][200][4]     @ 4000   (3200)
//   masks   [4][200][28][28]@ 7200   (627200)
#define OFF_ROIS  0
#define OFF_CLS   3200
#define OFF_DEL   4000
#define OFF_MSK   7200

// XLA rewrites x / const into x * (1/const) (algebraic simplifier).
// Reproduce bit-exactly: these fold at compile time to the same f32 XLA uses.
#define RCP_033  (1.0f / 0.33f)   // 66*r rounds to exactly 200.0f (division gives 199.99998)
#define RCP_01   (1.0f / 0.1f)    // exactly 10.0f
#define RCP_02   (1.0f / 0.2f)    // exactly 5.0f
#define RCP_27   (1.0f / 27.0f)

// ---------------- device scratch (no allocations allowed) ----------------
__device__ int            g_best[NIMG][NPROP];
__device__ unsigned char  g_posf[NIMG][NPROP];   // 0/1 bytes, NPROP%4==0
__device__ unsigned char  g_negf[NIMG][NPROP];
__device__ int            g_pos_idx[NIMG][PPOS];
__device__ int            g_pos_count[NIMG];
__device__ int            g_mask_fmt;   // 0=u8, 1=i32, 2=f32, 3=bf16

// ---------------- mask dtype probe helper (warp-collective) ----------------
__device__ __forceinline__ void probe_mask_fmt(const unsigned char* __restrict__ m,
                                               int lane) {
    int a = 0, b = 0, c = 0;
    for (int p = lane; p < 4096; p += 32) {
        unsigned char v = __ldg(m + p);
        if (v > 1) a = 1;
        if ((p & 3) == 1 && v != 0) b = 1;
        if ((p & 3) != 0 && v == 1) c = 1;
    }
    unsigned am = __ballot_sync(0xFFFFFFFFu, a);
    unsigned bm = __ballot_sync(0xFFFFFFFFu, b);
    unsigned cm = __ballot_sync(0xFFFFFFFFu, c);
    if (lane == 0) {
        int fmt;
        if (am) fmt = bm ? 3 : 2;
        else    fmt = cm ? 0 : 1;
        g_mask_fmt = fmt;
    }
}

__device__ __forceinline__ float mask_at(const void* m, int fmt, int idx) {
    switch (fmt) {
        case 0:  return (float)__ldg((const unsigned char*)m + idx);
        case 1:  return (float)__ldg((const int*)m + idx);
        case 3: {
            unsigned short u = __ldg((const unsigned short*)m + idx);
            __nv_bfloat16 v;
            *(unsigned short*)&v = u;
            return __bfloat162float(v);
        }
        default: return __ldg((const float*)m + idx);
    }
}

// ---------------- IoU / flags: one WARP per proposal ----------------
// 8 warps per block -> 8 proposals; grid (250, NIMG). Lane l computes GT l
// and GT l+32, then a butterfly reduction reproduces jnp.argmax first-max
// semantics (strictly greater wins; tie -> lower index).
__global__ void __launch_bounds__(256)
k_iou(const float* __restrict__ props,
      const int*   __restrict__ ids,
      const float* __restrict__ gtb) {
    const int img  = blockIdx.y;
    const int wid  = threadIdx.x >> 5;
    const int lane = threadIdx.x & 31;
    const int prop = blockIdx.x * 8 + wid;   // 250*8 = 2000

    __shared__ float4 sgt[MAXGT];
    __shared__ int    sfl[MAXGT];   // bit0: gt_valid, bit1: crowd
    if (threadIdx.x < MAXGT) {
        const float* g = gtb + (img * MAXGT + threadIdx.x) * 4;
        float4 b; b.x = g[0]; b.y = g[1]; b.z = g[2]; b.w = g[3];
        sgt[threadIdx.x] = b;
        int id = ids[img * MAXGT + threadIdx.x];
        bool bv = (b.x != 0.f) || (b.y != 0.f) || (b.z != 0.f) || (b.w != 0.f);
        sfl[threadIdx.x] = ((bv && id > 0) ? 1 : 0) | ((bv && id < 0) ? 2 : 0);
    }
    __syncthreads();

    // All lanes load the same proposal box (L1 broadcast).
    const float4 p = *(const float4*)(props + (img * NPROP + prop) * 4);
    const float py1 = p.x, px1 = p.y, py2 = p.z, px2 = p.w;
    const bool prop_valid = (py1 != 0.f) || (px1 != 0.f) || (py2 != 0.f) || (px2 != 0.f);
    const float a1 = __fmul_rn(__fsub_rn(py2, py1), __fsub_rn(px2, px1));

    float best = -INFINITY; int bi = 0;
    float crowd_max = -1.0f;
    #pragma unroll
    for (int t = 0; t < 2; ++t) {
        const int j = lane + 32 * t;
        float4 g = sgt[j];
        int fl = sfl[j];
        float ih = fmaxf(__fsub_rn(fminf(py2, g.z), fmaxf(py1, g.x)), 0.0f);
        float iw = fmaxf(__fsub_rn(fminf(px2, g.w), fmaxf(px1, g.y)), 0.0f);
        float inter = __fmul_rn(ih, iw);
        float a2 = __fmul_rn(__fsub_rn(g.z, g.x), __fsub_rn(g.w, g.y));
        float denom = __fadd_rn(__fsub_rn(__fadd_rn(a1, a2), inter), EPSF);
        float iou = __fdiv_rn(inter, denom);
        float ov = (fl & 1) ? iou : -1.0f;
        if (ov > best) { best = ov; bi = j; }   // j < j+32: first-max kept
        float cv = (fl & 2) ? iou : -1.0f;
        crowd_max = fmaxf(crowd_max, cv);
    }

    // Butterfly reduce: (max value, lowest index among maxima) + crowd max.
    #pragma unroll
    for (int off = 16; off > 0; off >>= 1) {
        float ob = __shfl_xor_sync(0xFFFFFFFFu, best, off);
        int   oi = __shfl_xor_sync(0xFFFFFFFFu, bi, off);
        float oc = __shfl_xor_sync(0xFFFFFFFFu, crowd_max, off);
        if (ob > best || (ob == best && oi < bi)) { best = ob; bi = oi; }
        crowd_max = fmaxf(crowd_max, oc);
    }

    if (lane == 0) {
        bool pos = (best >= 0.5f) && prop_valid;
        bool neg = (best < 0.5f) && (crowd_max < 0.001f) && prop_valid && !pos;
        g_best[img][prop] = bi;
        g_posf[img][prop] = pos ? 1 : 0;
        g_negf[img][prop] = neg ? 1 : 0;
    }
}

// ------- fused: stable first-k selection + rois/class/deltas emit -------
// Warp 0 scans packed uchar4 flag words: 128 proposals per round, 16 rounds.
__global__ void __launch_bounds__(256)
k_select_emit(const float* __restrict__ props,
              const int*   __restrict__ ids,
              const float* __restrict__ gtb,
              const unsigned char* __restrict__ masks_raw,
              float* __restrict__ out) {
    const int img = blockIdx.x;
    __shared__ int s_pos_idx[PPOS];
    __shared__ int s_neg_idx[NNEG];
    __shared__ int s_pos_count, s_neg_count;

    if (threadIdx.x < 32) {
        const int lane = threadIdx.x;
        const unsigned* pw = (const unsigned*)&g_posf[img][0];   // 500 words
        const unsigned* nw = (const unsigned*)&g_negf[img][0];
        const unsigned lt = (1u << lane) - 1u;
        int ptot = 0, ntot = 0;
        #pragma unroll 4
        for (int r = 0; r < 16; ++r) {           // 16*32 words = 2048 >= 500
            const int widx = r * 32 + lane;
            unsigned wp = (widx < 500) ? pw[widx] : 0u;
            unsigned wn = (widx < 500) ? nw[widx] : 0u;
            unsigned pm[4], nm[4];
            #pragma unroll
            for (int b = 0; b < 4; ++b) {
                pm[b] = __ballot_sync(0xFFFFFFFFu, (wp >> (8 * b)) & 1u);
                nm[b] = __ballot_sync(0xFFFFFFFFu, (wn >> (8 * b)) & 1u);
            }
            int plt = 0, nlt = 0, psum = 0, nsum = 0;
            #pragma unroll
            for (int b = 0; b < 4; ++b) {
                plt += __popc(pm[b] & lt);  psum += __popc(pm[b]);
                nlt += __popc(nm[b] & lt);  nsum += __popc(nm[b]);
            }
            int pbelow = 0, nbelow = 0;
            #pragma unroll
            for (int b = 0; b < 4; ++b) {
                if ((wp >> (8 * b)) & 1u) {
                    int rank = ptot + plt + pbelow;
                    if (rank < PPOS) s_pos_idx[rank] = widx * 4 + b;
                    pbelow++;
                }
                if ((wn >> (8 * b)) & 1u) {
                    int rank = ntot + nlt + nbelow;
                    if (rank < NNEG) s_neg_idx[rank] = widx * 4 + b;
                    nbelow++;
                }
            }
            ptot += psum;
            ntot += nsum;
        }
        if (lane == 0) {
            int pos_count = ptot < PPOS ? ptot : PPOS;
            int neg_target = (int)(__fmul_rn((float)pos_count, RCP_033)) - pos_count;
            int avail = ntot < NNEG ? ntot : NNEG;
            int neg_count = neg_target < 0 ? 0 : (neg_target < avail ? neg_target : avail);
            s_pos_count = pos_count;
            s_neg_count = neg_count;
            g_pos_count[img] = pos_count;
        }
    } else if (img == 0 && threadIdx.x >= 224) {
        probe_mask_fmt(masks_raw, threadIdx.x - 224);
    }
    __syncthreads();

    // Publish pos_idx for the mask kernel.
    if (threadIdx.x < PPOS) g_pos_idx[img][threadIdx.x] = s_pos_idx[threadIdx.x];

    const int k = threadIdx.x;   // 0..199 emit; others exit
    if (k >= NROIS) return;

    float r0 = 0.f, r1 = 0.f, r2 = 0.f, r3 = 0.f;
    float cls = 0.f;
    float d0 = 0.f, d1 = 0.f, d2 = 0.f, d3 = 0.f;

    if (k < PPOS) {
        if (k < s_pos_count) {
            int idx = s_pos_idx[k];
            const float* p = props + (img * NPROP + idx) * 4;
            r0 = p[0]; r1 = p[1]; r2 = p[2]; r3 = p[3];
            int bg = g_best[img][idx];
            cls = (float)ids[img * MAXGT + bg];
            const float* g = gtb + (img * MAXGT + bg) * 4;
            float gy1 = g[0], gx1 = g[1], gy2 = g[2], gx2 = g[3];
            float h  = fmaxf(__fsub_rn(r2, r0), EPSF);
            float w  = fmaxf(__fsub_rn(r3, r1), EPSF);
            float cy = __fadd_rn(r0, __fmul_rn(0.5f, h));
            float cx = __fadd_rn(r1, __fmul_rn(0.5f, w));
            float gh = fmaxf(__fsub_rn(gy2, gy1), EPSF);
            float gw = fmaxf(__fsub_rn(gx2, gx1), EPSF);
            float gcy = __fadd_rn(gy1, __fmul_rn(0.5f, gh));
            float gcx = __fadd_rn(gx1, __fmul_rn(0.5f, gw));
            d0 = __fmul_rn(__fdiv_rn(__fsub_rn(gcy, cy), h), RCP_01);
            d1 = __fmul_rn(__fdiv_rn(__fsub_rn(gcx, cx), w), RCP_01);
            d2 = __fmul_rn(logf(__fdiv_rn(gh, h)), RCP_02);
            d3 = __fmul_rn(logf(__fdiv_rn(gw, w)), RCP_02);
        }
    } else {
        int j = k - PPOS;
        if (j < s_neg_count) {
            int idx = s_neg_idx[j];
            const float* p = props + (img * NPROP + idx) * 4;
            r0 = p[0]; r1 = p[1]; r2 = p[2]; r3 = p[3];
        }
    }
    int row = img * NROIS + k;
    float* rois = out + OFF_ROIS + row * 4;
    rois[0] = r0; rois[1] = r1; rois[2] = r2; rois[3] = r3;
    out[OFF_CLS + row] = cls;
    float* del = out + OFF_DEL + row * 4;
    del[0] = d0; del[1] = d1; del[2] = d2; del[3] = d3;
}

// ---------------- mask crop-resize ----------------
__global__ void __launch_bounds__(MH * MW)
k_masks(const float* __restrict__ props,
        const void*  __restrict__ masks,
        float* __restrict__ out) {
    const int img = blockIdx.y;
    const int k   = blockIdx.x;   // 0..199
    const int t   = threadIdx.x;  // 0..783 pixel index
    float val = 0.0f;
    if (k < g_pos_count[img]) {   // k >= PPOS never passes (pos_count <= 66)
        int fmt = g_mask_fmt;
        int idx = g_pos_idx[img][k];
        int g   = g_best[img][idx];
        const float* p = props + (img * NPROP + idx) * 4;
        float y1 = p[0], x1 = p[1], y2 = p[2], x2 = p[3];
        int i = t / MW, j = t % MW;
        float iy = __fmul_rn((float)i, RCP_27);
        float ix = __fmul_rn((float)j, RCP_27);
        float ys = __fmul_rn(__fadd_rn(y1, __fmul_rn(iy, __fsub_rn(y2, y1))), (float)(HH - 1));
        float xs = __fmul_rn(__fadd_rn(x1, __fmul_rn(ix, __fsub_rn(x2, x1))), (float)(WW - 1));
        float y0f = floorf(ys), x0f = floorf(xs);
        float ly = __fsub_rn(ys, y0f);
        float lx = __fsub_rn(xs, x0f);
        int y0  = min(max((int)y0f, 0), HH - 1);
        int y1i = min(y0 + 1, HH - 1);
        int x0  = min(max((int)x0f, 0), WW - 1);
        int x1i = min(x0 + 1, WW - 1);
        int rowbase0 = (img * HH + y0)  * WW;
        int rowbase1 = (img * HH + y1i) * WW;
        float v00 = mask_at(masks, fmt, (rowbase0 + x0)  * MAXGT + g);
        float v01 = mask_at(masks, fmt, (rowbase0 + x1i) * MAXGT + g);
        float v10 = mask_at(masks, fmt, (rowbase1 + x0)  * MAXGT + g);
        float v11 = mask_at(masks, fmt, (rowbase1 + x1i) * MAXGT + g);
        float omlx = __fsub_rn(1.0f, lx);
        float omly = __fsub_rn(1.0f, ly);
        float top = __fadd_rn(__fmul_rn(v00, omlx), __fmul_rn(v01, lx));
        float bot = __fadd_rn(__fmul_rn(v10, omlx), __fmul_rn(v11, lx));
        val = rintf(__fadd_rn(__fmul_rn(top, omly), __fmul_rn(bot, ly)));  // round half-to-even
    }
    out[OFF_MSK + (img * NROIS + k) * (MH * MW) + t] = val;
}

// ---------------- launch ----------------
extern "C" void kernel_launch(void* const* d_in, const int* in_sizes, int n_in,
                              void* d_out, int out_size) {
    const float* props = (const float*)d_in[0];
    const int*   ids   = (const int*)  d_in[1];
    const float* gtb   = (const float*)d_in[2];
    const void*  masks = d_in[3];
    float* out = (float*)d_out;

    k_iou<<<dim3(NPROP / 8, NIMG), 256>>>(props, ids, gtb);
    k_select_emit<<<NIMG, 256>>>(props, ids, gtb,
                                 (const unsigned char*)masks, out);
    k_masks<<<dim3(NROIS, NIMG), MH * MW>>>(props, masks, out);
}